// round 8
// baseline (speedup 1.0000x reference)
#include <cuda_runtime.h>
#include <math.h>

#define RULES 512
#define FEAT  128
#define RES   5
#define BATCH 2048
#define WARPS_PER_BLOCK 16
#define THREADS (WARPS_PER_BLOCK * 32)          // 512 == RULES
#define BLOCKS  (BATCH / WARPS_PER_BLOCK)       // 128  (single wave on 148 SMs)
#define RULES_PER_LANE (RULES / 32)             // 16

#define LOG2E 1.4426950408889634f

__device__ __forceinline__ float ex2f(float v) {
    float r;
    asm("ex2.approx.f32 %0, %1;" : "=f"(r) : "f"(v));
    return r;
}
__device__ __forceinline__ float rcpf(float v) {
    float r;
    asm("rcp.approx.f32 %0, %1;" : "=f"(r) : "f"(v));
    return r;
}
__device__ __forceinline__ float warpSumF(float v) {
    #pragma unroll
    for (int o = 16; o; o >>= 1) v += __shfl_xor_sync(0xffffffffu, v, o);
    return v;
}

__global__ void __launch_bounds__(THREADS, 1)
fused_kernel(const float* __restrict__ x,
             const float* __restrict__ a,
             const float* __restrict__ bmat,
             const float* __restrict__ r,
             const float* __restrict__ d,
             float* __restrict__ out) {
    // Per-rule constants (fp32, log2-domain K; beliefs stored MINUS ONE)
    __shared__ float2 sK[RULES];        // (K0*log2e, K1*log2e)
    __shared__ float2 sBm01[RULES];     // beliefs0-1, beliefs1-1
    __shared__ float2 sBm23[RULES];     // beliefs2-1, beliefs3-1
    __shared__ float  sBm4[RULES];      // beliefs4-1

    const int t = threadIdx.x;
    const int l = t & 31;
    const int w = t >> 5;
    const int row = blockIdx.x * WARPS_PER_BLOCK + w;

    // Issue the global x load FIRST so DRAM latency overlaps the prep phase.
    const float4 xv = *reinterpret_cast<const float4*>(x + row * FEAT + l * 4);

    // ---- prep: thread t handles rule t (THREADS == RULES) ----
    const float ed = expf(d[0]);        // accurate: scales exponents of magnitude ~100s
    {
        float av = a[t];
        float k1 = 2.0f * ed * av;
        float k0 = r[t] - ed * 128.0f * av * av;
        sK[t] = make_float2(k0 * LOG2E, k1 * LOG2E);

        float bv[RES];
        float m = -1e30f;
        #pragma unroll
        for (int j = 0; j < RES; j++) { bv[j] = bmat[t * RES + j]; m = fmaxf(m, bv[j]); }
        float sum = 0.f;
        #pragma unroll
        for (int j = 0; j < RES; j++) { bv[j] = ex2f((bv[j] - m) * LOG2E); sum += bv[j]; }
        float inv = 1.0f / sum;
        sBm01[t] = make_float2(fmaf(bv[0], inv, -1.f), fmaf(bv[1], inv, -1.f));
        sBm23[t] = make_float2(fmaf(bv[2], inv, -1.f), fmaf(bv[3], inv, -1.f));
        sBm4[t]  = fmaf(bv[4], inv, -1.f);
    }
    __syncthreads();                    // the ONLY block barrier

    // ---- one warp = one batch row ----
    float x0 = xv.x * 0.2f, x1 = xv.y * 0.2f, x2 = xv.z * 0.2f, x3 = xv.w * 0.2f;
    float Sx  = x0 + x1 + x2 + x3;
    float Sxx = fmaf(x0, x0, fmaf(x1, x1, fmaf(x2, x2, x3 * x3)));
    // Fused butterfly: the two trees' SHFLs pipeline (indep chains)
    #pragma unroll
    for (int o = 16; o; o >>= 1) {
        Sx  += __shfl_xor_sync(0xffffffffu, Sx, o);
        Sxx += __shfl_xor_sync(0xffffffffu, Sxx, o);
    }
    const float C = ed * Sxx * LOG2E;   // common-mode term (cancels in ratios)

    // rule activations: log2-domain FFMA then raw EX2
    float aw[RULES_PER_LANE];
    float spart = 0.f;
    #pragma unroll
    for (int i = 0; i < RULES_PER_LANE; i++) {
        float2 K = sK[i * 32 + l];
        aw[i] = ex2f(fmaf(K.y, Sx, K.x) - C);   // dead rules underflow to 0, like ref
        spart += aw[i];
    }
    const float s = warpSumF(spart);
    const float inv_s = rcpf(s);

    // Divide-free combine:  with t_i = aw_i/s,
    //   num_j = prod_i(1 + t_i*(b_ij-1)),  den = prod_i(1 - t_i)
    // p_j = num_j/den, and den cancels in the final normalized expectation:
    //   out = sum_j (num_j - den) u_j / sum_j (num_j - den)
    float den = 1.f, n0 = 1.f, n1 = 1.f, n2 = 1.f, n3 = 1.f, n4 = 1.f;
    #pragma unroll
    for (int i = 0; i < RULES_PER_LANE; i++) {
        int rr = i * 32 + l;
        float ti = aw[i] * inv_s;
        float2 b01 = sBm01[rr];
        float2 b23 = sBm23[rr];
        float  b4  = sBm4[rr];
        den *= (1.0f - ti);
        n0 *= fmaf(ti, b01.x, 1.0f);
        n1 *= fmaf(ti, b01.y, 1.0f);
        n2 *= fmaf(ti, b23.x, 1.0f);
        n3 *= fmaf(ti, b23.y, 1.0f);
        n4 *= fmaf(ti, b4,    1.0f);
    }
    // 6 independent cross-lane product reductions (pipelined SHFL chains)
    #pragma unroll
    for (int o = 16; o; o >>= 1) {
        den *= __shfl_xor_sync(0xffffffffu, den, o);
        n0  *= __shfl_xor_sync(0xffffffffu, n0, o);
        n1  *= __shfl_xor_sync(0xffffffffu, n1, o);
        n2  *= __shfl_xor_sync(0xffffffffu, n2, o);
        n3  *= __shfl_xor_sync(0xffffffffu, n3, o);
        n4  *= __shfl_xor_sync(0xffffffffu, n4, o);
    }

    if (l == 0) {
        float b0 = n0 - den, b1 = n1 - den, b2 = n2 - den, b3 = n3 - den, b4 = n4 - den;
        float bsum = b0 + b1 + b2 + b3 + b4;
        float acc = fmaf(b0, -0.5f, 0.f);
        acc = fmaf(b2, 0.5f, acc);
        acc = fmaf(b3, 1.0f, acc);
        acc = fmaf(b4, 1.5f, acc);
        out[row] = __fdividef(acc, bsum);
    }
}

extern "C" void kernel_launch(void* const* d_in, const int* in_sizes, int n_in,
                              void* d_out, int out_size) {
    const float* x = (const float*)d_in[0];
    const float* a = (const float*)d_in[1];
    const float* b = (const float*)d_in[2];
    const float* r = (const float*)d_in[3];
    const float* d = (const float*)d_in[4];
    float* out = (float*)d_out;

    fused_kernel<<<BLOCKS, THREADS>>>(x, a, b, r, d, out);
}